// round 14
// baseline (speedup 1.0000x reference)
#include <cuda_runtime.h>
#include <cuda_bf16.h>
#include <math.h>

// ---------------- problem dims ----------------
#define BB 4
#define SS 1024
#define DD 128
#define HH 8
#define DH 16
#define NN 128
#define VV 32000
#define TOK (BB*SS)          // 4096

// ---------------- scratch (device globals; no allocation allowed) ----------
__device__ float g_we  [TOK*DD];          // 1/(1+|w_emb|) per token,dim
__device__ float g_be  [TOK*DD];          // b_emb gathered
__device__ float g_X   [TOK*DD];          // scan output
__device__ float g_q   [BB*HH*SS*32];     // (b,h,s,32)
__device__ float g_k   [BB*HH*SS*32];
__device__ float g_S   [BB*HH*SS*SS];     // raw scores (lower-tri only valid)
__device__ float g_A   [BB*SS*SS];        // head-summed softmax weights
__device__ float g_ctx [TOK*DD];
__device__ float g_x   [TOK*DD];          // post-context x (then updated by silu)
__device__ float g_cs  [TOK*NN];
__device__ float g_ssum[TOK*NN];
__device__ float g_tcos[SS];
__device__ float g_tsin[SS];
__device__ float g_rres[DD*NN];           // [d][n] = 1/(1+|W_res[n][d]|)
__device__ float g_bres[DD*NN];           // [d][n] = B_res[n][d]
__device__ float g_WctxT [DD*DD];         // [e][d] = W_ctx[d][e]
__device__ float g_WrealT[NN*DD];         // [n][d] = W_real[d][n]
__device__ float g_WimagT[NN*DD];         // [n][d] = W_imag[d][n]

// ---------------- prep: transposes + accurate tphi trig table --------------
__global__ void k_prep(const float* __restrict__ Wctx, const float* __restrict__ Wres,
                       const float* __restrict__ Bres, const float* __restrict__ Wreal,
                       const float* __restrict__ Wimag)
{
    int idx = blockIdx.x * 256 + threadIdx.x;      // < 16384
    int i = idx >> 7, j = idx & 127;
    g_WctxT [idx] = Wctx [j*128 + i];
    g_WrealT[idx] = Wreal[j*128 + i];
    g_WimagT[idx] = Wimag[j*128 + i];
    g_rres  [idx] = 1.0f / (1.0f + fabsf(Wres[j*128 + i]));
    g_bres  [idx] = Bres[j*128 + i];
    if (idx < SS) {
        float tphi = (float)idx * 1.6180339887498949f;   // matches f32 t*PHI
        float s, c; sincosf(tphi, &s, &c);               // accurate large-arg
        g_tsin[idx] = s; g_tcos[idx] = c;
    }
}

// ---------------- gather embedding rows (coalesced) ------------------------
__global__ void k_gather(const int* __restrict__ ids, const float* __restrict__ emb)
{
    int gid = blockIdx.x * 256 + threadIdx.x;     // < 524288
    int tok = gid >> 7, d = gid & 127;
    int idx = ids[tok];
    float w = emb[idx*256 + d];
    g_we[gid] = 1.0f / (1.0f + fabsf(w));         // precompute reciprocal
    g_be[gid] = emb[idx*256 + 128 + d];
}

// ---------------- sequential scan: 512 independent chains ------------------
__global__ void k_scan()
{
    int b = blockIdx.x;
    int d = threadIdx.x;
    const float* wr = &g_we[b*SS*DD + d];
    const float* br = &g_be[b*SS*DD + d];
    float wbuf[16], bbuf[16];
#pragma unroll
    for (int p = 0; p < 16; p++) { wbuf[p] = wr[p*128]; bbuf[p] = br[p*128]; }
    float hr = 0.f, hi = 0.f;
    float* xp = &g_X[b*SS*DD + d];
    for (int t0 = 0; t0 < SS; t0 += 16) {
#pragma unroll
        for (int u = 0; u < 16; u++) {
            int t = t0 + u;
            float rwl = wbuf[u], bbv = bbuf[u];
            if (t + 16 < SS) { wbuf[u] = wr[(t+16)*128]; bbuf[u] = br[(t+16)*128]; }
            float cT = g_tcos[t], sT = g_tsin[t];
            float ur = fmaf(hr, rwl, bbv);
            float ui = fmaf(hi, rwl, bbv);
            float sur, cur, sui, cui;
            __sincosf(ur, &sur, &cur);            // small args -> accurate
            __sincosf(ui, &sui, &cui);
            // cos/sin(u + tphi) via rotation with accurate (cT,sT)
            float cr  = cur*cT - sur*sT;
            float sr  = sur*cT + cur*sT;
            float ci2 = cui*cT - sui*sT;
            float si2 = sui*cT + cui*sT;
            float nr = cr*ci2 - sr*si2;
            float ni = cr*si2 + sr*ci2;
            xp[t*128] = nr + ni;
            hr = nr; hi = ni;
        }
    }
}

// ---------------- q,k construction -----------------------------------------
__global__ void k_qk(const float* __restrict__ wq, const float* __restrict__ bq,
                     const float* __restrict__ wk, const float* __restrict__ bk)
{
    int gid = blockIdx.x * 256 + threadIdx.x;     // < 524288
    int tok = gid >> 7, hd = gid & 127;
    int s = tok & (SS-1), b = tok >> 10;
    float X = g_X[gid];
    float rq = 1.0f / (1.0f + fabsf(wq[hd]));
    float rk = 1.0f / (1.0f + fabsf(wk[hd]));
    float uq = fmaf(X, rq, bq[hd]);
    float uk = fmaf(X, rk, bk[hd]);
    float cT = g_tcos[s], sT = g_tsin[s];
    float su, cu; __sincosf(uq, &su, &cu);
    float cq = cu*cT - su*sT;
    float sq = su*cT + cu*sT;
    float sk2, ck2; __sincosf(uk, &sk2, &ck2);
    int h = hd >> 4, ddv = hd & 15;
    int base = ((b*HH + h)*SS + s)*32 + ddv;
    g_q[base] = cq;  g_q[base+16] = sq;
    g_k[base] = ck2; g_k[base+16] = sk2;
}

// ---------------- scores (strict lower tri, tiled, culled) -----------------
__global__ __launch_bounds__(256) void k_scores()
{
    int jt = blockIdx.x, it = blockIdx.y, bh = blockIdx.z;
    if (jt > it) return;
    int i0 = it*64, j0 = jt*64;
    __shared__ __align__(16) float qs[32][64];
    __shared__ __align__(16) float ks[32][64];
    int tid = threadIdx.x;
    {
        int lin = tid * 8; int row = lin >> 5; int col = lin & 31;
        const float* qp = &g_q[(bh*SS + i0 + row)*32 + col];
        const float* kp = &g_k[(bh*SS + j0 + row)*32 + col];
        float4 q0 = *(const float4*)qp, q1 = *(const float4*)(qp+4);
        float4 k0 = *(const float4*)kp, k1 = *(const float4*)(kp+4);
        qs[col+0][row]=q0.x; qs[col+1][row]=q0.y; qs[col+2][row]=q0.z; qs[col+3][row]=q0.w;
        qs[col+4][row]=q1.x; qs[col+5][row]=q1.y; qs[col+6][row]=q1.z; qs[col+7][row]=q1.w;
        ks[col+0][row]=k0.x; ks[col+1][row]=k0.y; ks[col+2][row]=k0.z; ks[col+3][row]=k0.w;
        ks[col+4][row]=k1.x; ks[col+5][row]=k1.y; ks[col+6][row]=k1.z; ks[col+7][row]=k1.w;
    }
    __syncthreads();
    int ti = tid >> 4, tj = tid & 15;
    float acc[4][4] = {};
#pragma unroll
    for (int kk = 0; kk < 32; kk++) {
        float4 av = *(const float4*)&qs[kk][ti*4];
        float4 bv = *(const float4*)&ks[kk][tj*4];
        float a[4] = {av.x, av.y, av.z, av.w};
        float bb[4] = {bv.x, bv.y, bv.z, bv.w};
#pragma unroll
        for (int x = 0; x < 4; x++)
#pragma unroll
            for (int y = 0; y < 4; y++) acc[x][y] = fmaf(a[x], bb[y], acc[x][y]);
    }
    const float sc = 0.17677669529663687f;  // 1/sqrt(2*dh)
#pragma unroll
    for (int x = 0; x < 4; x++) {
        int i = i0 + ti*4 + x;
#pragma unroll
        for (int y = 0; y < 4; y++) {
            int j = j0 + tj*4 + y;
            if (j < i) g_S[(bh*SS + i)*SS + j] = acc[x][y] * sc;
        }
    }
}

// ---------------- block reductions -----------------------------------------
__device__ __forceinline__ float blockMax(float v, float* red)
{
#pragma unroll
    for (int o = 16; o > 0; o >>= 1) v = fmaxf(v, __shfl_xor_sync(0xffffffffu, v, o));
    __syncthreads();
    if ((threadIdx.x & 31) == 0) red[threadIdx.x >> 5] = v;
    __syncthreads();
    if (threadIdx.x < 32) {
        float x = (threadIdx.x < 8) ? red[threadIdx.x] : -1e30f;
#pragma unroll
        for (int o = 4; o > 0; o >>= 1) x = fmaxf(x, __shfl_xor_sync(0xffffffffu, x, o));
        if (threadIdx.x == 0) red[0] = x;
    }
    __syncthreads();
    return red[0];
}
__device__ __forceinline__ float blockSum(float v, float* red)
{
#pragma unroll
    for (int o = 16; o > 0; o >>= 1) v += __shfl_xor_sync(0xffffffffu, v, o);
    __syncthreads();
    if ((threadIdx.x & 31) == 0) red[threadIdx.x >> 5] = v;
    __syncthreads();
    if (threadIdx.x < 32) {
        float x = (threadIdx.x < 8) ? red[threadIdx.x] : 0.0f;
#pragma unroll
        for (int o = 4; o > 0; o >>= 1) x += __shfl_xor_sync(0xffffffffu, x, o);
        if (threadIdx.x == 0) red[0] = x;
    }
    __syncthreads();
    return red[0];
}

// ---------------- softmax + head-sum into A --------------------------------
__global__ __launch_bounds__(256) void k_softmax()
{
    int i = blockIdx.x, b = blockIdx.y, tid = threadIdx.x;
    __shared__ float red[32];
    float acc[4] = {0.f, 0.f, 0.f, 0.f};
    if (i > 0) {
        for (int h = 0; h < HH; h++) {
            int base = ((b*HH + h)*SS + i)*SS;
            float sv[4]; float m = -1e30f;
#pragma unroll
            for (int c = 0; c < 4; c++) {
                int j = c*256 + tid;
                sv[c] = (j < i) ? g_S[base + j] : -1e30f;
                m = fmaxf(m, sv[c]);
            }
            m = blockMax(m, red);
            float z = 0.f;
#pragma unroll
            for (int c = 0; c < 4; c++) {
                int j = c*256 + tid;
                float e = (j < i) ? expf(sv[c] - m) : 0.0f;
                sv[c] = e; z += e;
            }
            z = blockSum(z, red);
            float iz = 1.0f / z;
#pragma unroll
            for (int c = 0; c < 4; c++) acc[c] = fmaf(sv[c], iz, acc[c]);
        }
    }
#pragma unroll
    for (int c = 0; c < 4; c++)
        g_A[(b*SS + i)*SS + c*256 + tid] = acc[c];
}

// ---------------- context = A @ X ------------------------------------------
__global__ __launch_bounds__(256) void k_ctxgemm()
{
    int b = blockIdx.y;
    int i0 = blockIdx.x * 32;
    __shared__ __align__(16) float As[32][64];
    __shared__ __align__(16) float Xs[64][128];
    int tid = threadIdx.x;
    int ri = (tid >> 4) * 2;
    int ci = (tid & 15) * 8;
    float acc[2][8] = {};
    for (int j0 = 0; j0 < SS; j0 += 64) {
        {
            int r = tid >> 3; int c = (tid & 7) * 8;
            const float* p = &g_A[(b*SS + i0 + r)*SS + j0 + c];
            *(float4*)&As[r][c]   = *(const float4*)p;
            *(float4*)&As[r][c+4] = *(const float4*)(p+4);
        }
        {
            int r = tid >> 2; int c = (tid & 3) * 32;
            const float4* p = (const float4*)&g_X[(b*SS + j0 + r)*128 + c];
            float4* q = (float4*)&Xs[r][c];
#pragma unroll
            for (int x = 0; x < 8; x++) q[x] = p[x];
        }
        __syncthreads();
#pragma unroll 8
        for (int jj = 0; jj < 64; jj++) {
            float a0 = As[ri][jj], a1 = As[ri+1][jj];
            float4 b0 = *(const float4*)&Xs[jj][ci];
            float4 b1 = *(const float4*)&Xs[jj][ci+4];
            float bv[8] = {b0.x,b0.y,b0.z,b0.w,b1.x,b1.y,b1.z,b1.w};
#pragma unroll
            for (int y = 0; y < 8; y++) {
                acc[0][y] = fmaf(a0, bv[y], acc[0][y]);
                acc[1][y] = fmaf(a1, bv[y], acc[1][y]);
            }
        }
        __syncthreads();
    }
#pragma unroll
    for (int r = 0; r < 2; r++) {
        float* cp = &g_ctx[(b*SS + i0 + ri + r)*128 + ci];
        *(float4*)cp     = make_float4(acc[r][0],acc[r][1],acc[r][2],acc[r][3]);
        *(float4*)(cp+4) = make_float4(acc[r][4],acc[r][5],acc[r][6],acc[r][7]);
    }
}

// ---------------- x = X + context @ W_ctx^T ---------------------------------
__global__ __launch_bounds__(256) void k_ctxproj()
{
    int tt = threadIdx.x >> 7, d = threadIdx.x & 127;
    int tok = blockIdx.x * 2 + tt;
    __shared__ float cs[2][128];
    cs[tt][d] = g_ctx[tok*128 + d];
    __syncthreads();
    float acc = 0.f;
#pragma unroll 8
    for (int e = 0; e < 128; e++) acc = fmaf(cs[tt][e], g_WctxT[e*128 + d], acc);
    g_x[tok*128 + d] = g_X[tok*128 + d] + acc;
}

// ---------------- phasor sums (tphi factored out) ---------------------------
__global__ __launch_bounds__(256) void k_sincos()
{
    int tt = threadIdx.x >> 7, n = threadIdx.x & 127;
    int tok = blockIdx.x * 2 + tt;
    __shared__ float xs[2][128];
    xs[tt][n] = g_x[tok*128 + n];
    __syncthreads();
    float Ca = 0.f, Sa = 0.f;
#pragma unroll 4
    for (int d = 0; d < 128; d++) {
        float a = fmaf(xs[tt][d], g_rres[d*128 + n], g_bres[d*128 + n]);
        float s, c; __sincosf(a, &s, &c);
        Ca += c; Sa += s;
    }
    int sidx = tok & (SS-1);
    float cT = g_tcos[sidx], sT = g_tsin[sidx];
    g_cs  [tok*128 + n] = cT*Ca - sT*Sa;
    g_ssum[tok*128 + n] = cT*Sa + sT*Ca;
}

// ---------------- silu residual ---------------------------------------------
__global__ __launch_bounds__(256) void k_silu()
{
    int tt = threadIdx.x >> 7, d = threadIdx.x & 127;
    int tok = blockIdx.x * 2 + tt;
    __shared__ float cs[2][128];
    __shared__ float ss[2][128];
    cs[tt][d] = g_cs  [tok*128 + d];
    ss[tt][d] = g_ssum[tok*128 + d];
    __syncthreads();
    float acc = 0.f;
#pragma unroll 4
    for (int n = 0; n < 128; n++) {
        acc = fmaf(cs[tt][n], g_WrealT[n*128 + d], acc);
        acc = fmaf(ss[tt][n], g_WimagT[n*128 + d], acc);
    }
    float sv = acc / (1.0f + expf(-acc));
    g_x[tok*128 + d] += sv;
}

// ---------------- final GEMM: out = x @ W_out^T (4096 x 32000 x 128) --------
__global__ __launch_bounds__(256, 2) void k_gemm_out(const float* __restrict__ W,
                                                     float* __restrict__ out)
{
    const int bn = blockIdx.x * 128;
    const int bm = blockIdx.y * 128;
    __shared__ __align__(16) float As[2][16][128];
    __shared__ __align__(16) float Bs[2][16][128];
    const int tid = threadIdx.x;
    const int lr = tid >> 1;
    const int lk = (tid & 1) * 8;
    const int tx = tid & 15;
    const int ty = tid >> 4;
    float acc[8][8] = {};
    float4 ra0, ra1, rb0, rb1;
    {
        const float* xa = &g_x[(bm + lr)*128 + lk];
        ra0 = *(const float4*)xa; ra1 = *(const float4*)(xa + 4);
        const float* wb = &W[(bn + lr)*128 + lk];
        rb0 = *(const float4*)wb; rb1 = *(const float4*)(wb + 4);
    }
    As[0][lk+0][lr]=ra0.x; As[0][lk+1][lr]=ra0.y; As[0][lk+2][lr]=ra0.z; As[0][lk+3][lr]=ra0.w;
    As[0][lk+4][lr]=ra1.x; As[0][lk+5][lr]=ra1.y; As[0][lk+6][lr]=ra1.z; As[0][lk+7][lr]=ra1.w;
    Bs[0][lk+0][lr]=rb0.x; Bs[0][lk+1][lr]=rb0.y; Bs[0][lk+2][lr]=rb0.z; Bs[0][lk+3][lr]=rb0.w;
    Bs[0][lk+4][lr]=rb1.x; Bs[0][lk+5][lr]=rb1.y; Bs[0][lk+6][lr]=rb1.z; Bs[0][lk+7][lr]=rb1.w;
    __syncthreads();
#pragma unroll
    for (int st = 0; st < 8; st++) {
        int nxt = st + 1;
        if (nxt < 8) {
            const float* xa = &g_x[(bm + lr)*128 + nxt*16 + lk];
            ra0 = *(const float4*)xa; ra1 = *(const float4*)(xa + 4);
            const float* wb = &W[(bn + lr)*128 + nxt*16 + lk];
            rb0 = *(const float4*)wb; rb1 = *(const float4*)(wb + 4);
        }
        int buf = st & 1;
#pragma unroll
        for (int kk = 0; kk < 16; kk++) {
            float4 a0 = *(const float4*)&As[buf][kk][ty*8];
            float4 a1 = *(const float4*)&As[buf][kk][ty*8 + 4];
            float4 b0 = *(const float4*)&Bs[buf][kk][tx*8];
            float4 b1 = *(const float4*)&Bs[buf][kk][tx*8 + 4];
            float a[8] = {a0.x,a0.y,a0.z,a0.w,a1.x,a1.y,a1.z,a1.w};
            float bv[8] = {b0.x,b0.y,b0.z,b0.w,b1.x,b1.y,b1.z,b1.w};
#pragma unroll
            for (int i = 0; i < 8; i++)
#pragma unroll
                for (int j = 0; j < 8; j++)
                    acc[i][j] = fmaf(a[i], bv[j], acc[i][j]);
        }
        if (nxt < 8) {
            int nb = nxt & 1;
            As[nb][lk+0][lr]=ra0.x; As[nb][lk+1][lr]=ra0.y; As[nb][lk+2][lr]=ra0.z; As[nb][lk+3][lr]=ra0.w;
            As[nb][lk+4][lr]=ra1.x; As[nb][lk+5][lr]=ra1.y; As[nb][lk+6][lr]=ra1.z; As[nb][lk+7][lr]=ra1.w;
            Bs[nb][lk+0][lr]=rb0.x; Bs[nb][lk+1][lr]=rb0.y; Bs[nb][lk+2][lr]=rb0.z; Bs[nb][lk+3][lr]=rb0.w;
            Bs[nb][lk+4][lr]=rb1.x; Bs[nb][lk+5][lr]=rb1.y; Bs[nb][lk+6][lr]=rb1.z; Bs[nb][lk+7][lr]=rb1.w;
            __syncthreads();
        }
    }
#pragma unroll
    for (int i = 0; i < 8; i++) {
        size_t m = (size_t)(bm + ty*8 + i);
        float* op = &out[m * VV + bn + tx*8];
        *(float4*)op     = make_float4(acc[i][0],acc[i][1],acc[i][2],acc[i][3]);
        *(float4*)(op+4) = make_float4(acc[i][4],acc[i][5],acc[i][6],acc[i][7]);
    }
}

// ---------------- launch ----------------------------------------------------
extern "C" void kernel_launch(void* const* d_in, const int* in_sizes, int n_in,
                              void* d_out, int out_size)
{
    const int*   ids   = (const int*)  d_in[0];
    const float* emb   = (const float*)d_in[1];
    const float* wq    = (const float*)d_in[2];
    const float* bq    = (const float*)d_in[3];
    const float* wk    = (const float*)d_in[4];
    const float* bk    = (const float*)d_in[5];
    const float* Wctx  = (const float*)d_in[6];
    const float* Wres  = (const float*)d_in[7];
    const float* Bres  = (const float*)d_in[8];
    const float* Wreal = (const float*)d_in[9];
    const float* Wimag = (const float*)d_in[10];
    const float* Wout  = (const float*)d_in[11];
    float* out = (float*)d_out;

    k_prep   <<<64,   256>>>(Wctx, Wres, Bres, Wreal, Wimag);
    k_gather <<<2048, 256>>>(ids, emb);
    k_scan   <<<4,    128>>>();
    k_qk     <<<2048, 256>>>(wq, bq, wk, bk);
    k_scores <<<dim3(16, 16, 32), 256>>>();
    k_softmax<<<dim3(1024, 4),    256>>>();
    k_ctxgemm<<<dim3(32, 4),      256>>>();
    k_ctxproj<<<2048, 256>>>();
    k_sincos <<<2048, 256>>>();
    k_silu   <<<2048, 256>>>();
    k_gemm_out<<<dim3(VV/128, TOK/128), 256>>>(Wout, out);
    (void)in_sizes; (void)n_in; (void)out_size;
}

// round 17
// speedup vs baseline: 1.6596x; 1.6596x over previous
#include <cuda_runtime.h>
#include <cuda_bf16.h>
#include <math.h>
#include <stdint.h>

// ---------------- problem dims ----------------
#define BB 4
#define SS 1024
#define DD 128
#define HH 8
#define DH 16
#define NN 128
#define VV 32000
#define TOK (BB*SS)          // 4096
#define GK 384               // split-K for tensor-core GEMM (3 x 128)

// ---------------- scratch (device globals; no allocation allowed) ----------
__device__ float g_we  [TOK*DD];
__device__ float g_be  [TOK*DD];
__device__ float g_X   [TOK*DD];
__device__ float g_q   [BB*HH*SS*32];
__device__ float g_k   [BB*HH*SS*32];
__device__ float g_S   [BB*HH*SS*SS];
__device__ float g_A   [BB*SS*SS];
__device__ float g_ctx [TOK*DD];
__device__ float g_x   [TOK*DD];
__device__ float g_cs  [TOK*NN];
__device__ float g_ssum[TOK*NN];
__device__ float g_tcos[SS];
__device__ float g_tsin[SS];
__device__ float g_rres[DD*NN];
__device__ float g_bres[DD*NN];
__device__ float g_WctxT [DD*DD];
__device__ float g_WrealT[NN*DD];
__device__ float g_WimagT[NN*DD];
// split-bf16 operands for the mma.sync vocab GEMM
__device__ __align__(16) __nv_bfloat16 g_xsplit[TOK*GK];   // [tok][hi|hi|lo]
__device__ __align__(16) __nv_bfloat16 g_wsplit[VV*GK];    // [n]  [hi|lo|hi]

__device__ __forceinline__ uint32_t smem_u32(const void* p) {
    uint32_t a;
    asm("{ .reg .u64 t; cvta.to.shared.u64 t, %1; cvt.u32.u64 %0, t; }" : "=r"(a) : "l"(p));
    return a;
}

// ---------------- prep ------------------------------------------------------
__global__ void k_prep(const float* __restrict__ Wctx, const float* __restrict__ Wres,
                       const float* __restrict__ Bres, const float* __restrict__ Wreal,
                       const float* __restrict__ Wimag)
{
    int idx = blockIdx.x * 256 + threadIdx.x;
    int i = idx >> 7, j = idx & 127;
    g_WctxT [idx] = Wctx [j*128 + i];
    g_WrealT[idx] = Wreal[j*128 + i];
    g_WimagT[idx] = Wimag[j*128 + i];
    g_rres  [idx] = 1.0f / (1.0f + fabsf(Wres[j*128 + i]));
    g_bres  [idx] = Bres[j*128 + i];
    if (idx < SS) {
        float tphi = (float)idx * 1.6180339887498949f;
        float s, c; sincosf(tphi, &s, &c);
        g_tsin[idx] = s; g_tcos[idx] = c;
    }
}

// ---------------- gather ----------------------------------------------------
__global__ void k_gather(const int* __restrict__ ids, const float* __restrict__ emb)
{
    int gid = blockIdx.x * 256 + threadIdx.x;
    int tok = gid >> 7, d = gid & 127;
    int idx = ids[tok];
    float w = emb[idx*256 + d];
    g_we[gid] = 1.0f / (1.0f + fabsf(w));
    g_be[gid] = emb[idx*256 + 128 + d];
}

// ---------------- scan ------------------------------------------------------
__global__ void k_scan()
{
    int b = blockIdx.x;
    int d = threadIdx.x;
    const float* wr = &g_we[b*SS*DD + d];
    const float* br = &g_be[b*SS*DD + d];
    float wbuf[16], bbuf[16];
#pragma unroll
    for (int p = 0; p < 16; p++) { wbuf[p] = wr[p*128]; bbuf[p] = br[p*128]; }
    float hr = 0.f, hi = 0.f;
    float* xp = &g_X[b*SS*DD + d];
    for (int t0 = 0; t0 < SS; t0 += 16) {
#pragma unroll
        for (int u = 0; u < 16; u++) {
            int t = t0 + u;
            float rwl = wbuf[u], bbv = bbuf[u];
            if (t + 16 < SS) { wbuf[u] = wr[(t+16)*128]; bbuf[u] = br[(t+16)*128]; }
            float cT = g_tcos[t], sT = g_tsin[t];
            float ur = fmaf(hr, rwl, bbv);
            float ui = fmaf(hi, rwl, bbv);
            float sur, cur, sui, cui;
            __sincosf(ur, &sur, &cur);
            __sincosf(ui, &sui, &cui);
            float cr  = cur*cT - sur*sT;
            float sr  = sur*cT + cur*sT;
            float ci2 = cui*cT - sui*sT;
            float si2 = sui*cT + cui*sT;
            float nr = cr*ci2 - sr*si2;
            float ni = cr*si2 + sr*ci2;
            xp[t*128] = nr + ni;
            hr = nr; hi = ni;
        }
    }
}

// ---------------- q,k -------------------------------------------------------
__global__ void k_qk(const float* __restrict__ wq, const float* __restrict__ bq,
                     const float* __restrict__ wk, const float* __restrict__ bk)
{
    int gid = blockIdx.x * 256 + threadIdx.x;
    int tok = gid >> 7, hd = gid & 127;
    int s = tok & (SS-1), b = tok >> 10;
    float X = g_X[gid];
    float rq = 1.0f / (1.0f + fabsf(wq[hd]));
    float rk = 1.0f / (1.0f + fabsf(wk[hd]));
    float uq = fmaf(X, rq, bq[hd]);
    float uk = fmaf(X, rk, bk[hd]);
    float cT = g_tcos[s], sT = g_tsin[s];
    float su, cu; __sincosf(uq, &su, &cu);
    float cq = cu*cT - su*sT;
    float sq = su*cT + cu*sT;
    float sk2, ck2; __sincosf(uk, &sk2, &ck2);
    int h = hd >> 4, ddv = hd & 15;
    int base = ((b*HH + h)*SS + s)*32 + ddv;
    g_q[base] = cq;  g_q[base+16] = sq;
    g_k[base] = ck2; g_k[base+16] = sk2;
}

// ---------------- scores ----------------------------------------------------
__global__ __launch_bounds__(256) void k_scores()
{
    int jt = blockIdx.x, it = blockIdx.y, bh = blockIdx.z;
    if (jt > it) return;
    int i0 = it*64, j0 = jt*64;
    __shared__ __align__(16) float qs[32][64];
    __shared__ __align__(16) float ks[32][64];
    int tid = threadIdx.x;
    {
        int lin = tid * 8; int row = lin >> 5; int col = lin & 31;
        const float* qp = &g_q[(bh*SS + i0 + row)*32 + col];
        const float* kp = &g_k[(bh*SS + j0 + row)*32 + col];
        float4 q0 = *(const float4*)qp, q1 = *(const float4*)(qp+4);
        float4 k0 = *(const float4*)kp, k1 = *(const float4*)(kp+4);
        qs[col+0][row]=q0.x; qs[col+1][row]=q0.y; qs[col+2][row]=q0.z; qs[col+3][row]=q0.w;
        qs[col+4][row]=q1.x; qs[col+5][row]=q1.y; qs[col+6][row]=q1.z; qs[col+7][row]=q1.w;
        ks[col+0][row]=k0.x; ks[col+1][row]=k0.y; ks[col+2][row]=k0.z; ks[col+3][row]=k0.w;
        ks[col+4][row]=k1.x; ks[col+5][row]=k1.y; ks[col+6][row]=k1.z; ks[col+7][row]=k1.w;
    }
    __syncthreads();
    int ti = tid >> 4, tj = tid & 15;
    float acc[4][4] = {};
#pragma unroll
    for (int kk = 0; kk < 32; kk++) {
        float4 av = *(const float4*)&qs[kk][ti*4];
        float4 bv = *(const float4*)&ks[kk][tj*4];
        float a[4] = {av.x, av.y, av.z, av.w};
        float bb[4] = {bv.x, bv.y, bv.z, bv.w};
#pragma unroll
        for (int x = 0; x < 4; x++)
#pragma unroll
            for (int y = 0; y < 4; y++) acc[x][y] = fmaf(a[x], bb[y], acc[x][y]);
    }
    const float sc = 0.17677669529663687f;
#pragma unroll
    for (int x = 0; x < 4; x++) {
        int i = i0 + ti*4 + x;
#pragma unroll
        for (int y = 0; y < 4; y++) {
            int j = j0 + tj*4 + y;
            if (j < i) g_S[(bh*SS + i)*SS + j] = acc[x][y] * sc;
        }
    }
}

// ---------------- reductions -------------------------------------------------
__device__ __forceinline__ float blockMax(float v, float* red)
{
#pragma unroll
    for (int o = 16; o > 0; o >>= 1) v = fmaxf(v, __shfl_xor_sync(0xffffffffu, v, o));
    __syncthreads();
    if ((threadIdx.x & 31) == 0) red[threadIdx.x >> 5] = v;
    __syncthreads();
    if (threadIdx.x < 32) {
        float x = (threadIdx.x < 8) ? red[threadIdx.x] : -1e30f;
#pragma unroll
        for (int o = 4; o > 0; o >>= 1) x = fmaxf(x, __shfl_xor_sync(0xffffffffu, x, o));
        if (threadIdx.x == 0) red[0] = x;
    }
    __syncthreads();
    return red[0];
}
__device__ __forceinline__ float blockSum(float v, float* red)
{
#pragma unroll
    for (int o = 16; o > 0; o >>= 1) v += __shfl_xor_sync(0xffffffffu, v, o);
    __syncthreads();
    if ((threadIdx.x & 31) == 0) red[threadIdx.x >> 5] = v;
    __syncthreads();
    if (threadIdx.x < 32) {
        float x = (threadIdx.x < 8) ? red[threadIdx.x] : 0.0f;
#pragma unroll
        for (int o = 4; o > 0; o >>= 1) x += __shfl_xor_sync(0xffffffffu, x, o);
        if (threadIdx.x == 0) red[0] = x;
    }
    __syncthreads();
    return red[0];
}

// ---------------- softmax + head-sum ----------------------------------------
__global__ __launch_bounds__(256) void k_softmax()
{
    int i = blockIdx.x, b = blockIdx.y, tid = threadIdx.x;
    __shared__ float red[32];
    float acc[4] = {0.f, 0.f, 0.f, 0.f};
    if (i > 0) {
        for (int h = 0; h < HH; h++) {
            int base = ((b*HH + h)*SS + i)*SS;
            float sv[4]; float m = -1e30f;
#pragma unroll
            for (int c = 0; c < 4; c++) {
                int j = c*256 + tid;
                sv[c] = (j < i) ? g_S[base + j] : -1e30f;
                m = fmaxf(m, sv[c]);
            }
            m = blockMax(m, red);
            float z = 0.f;
#pragma unroll
            for (int c = 0; c < 4; c++) {
                int j = c*256 + tid;
                float e = (j < i) ? expf(sv[c] - m) : 0.0f;
                sv[c] = e; z += e;
            }
            z = blockSum(z, red);
            float iz = 1.0f / z;
#pragma unroll
            for (int c = 0; c < 4; c++) acc[c] = fmaf(sv[c], iz, acc[c]);
        }
    }
#pragma unroll
    for (int c = 0; c < 4; c++)
        g_A[(b*SS + i)*SS + c*256 + tid] = acc[c];
}

// ---------------- context = A @ X -------------------------------------------
__global__ __launch_bounds__(256) void k_ctxgemm()
{
    int b = blockIdx.y;
    int i0 = blockIdx.x * 32;
    __shared__ __align__(16) float As[32][64];
    __shared__ __align__(16) float Xs[64][128];
    int tid = threadIdx.x;
    int ri = (tid >> 4) * 2;
    int ci = (tid & 15) * 8;
    float acc[2][8] = {};
    for (int j0 = 0; j0 < SS; j0 += 64) {
        {
            int r = tid >> 3; int c = (tid & 7) * 8;
            const float* p = &g_A[(b*SS + i0 + r)*SS + j0 + c];
            *(float4*)&As[r][c]   = *(const float4*)p;
            *(float4*)&As[r][c+4] = *(const float4*)(p+4);
        }
        {
            int r = tid >> 2; int c = (tid & 3) * 32;
            const float4* p = (const float4*)&g_X[(b*SS + j0 + r)*128 + c];
            float4* q = (float4*)&Xs[r][c];
#pragma unroll
            for (int x = 0; x < 8; x++) q[x] = p[x];
        }
        __syncthreads();
#pragma unroll 8
        for (int jj = 0; jj < 64; jj++) {
            float a0 = As[ri][jj], a1 = As[ri+1][jj];
            float4 b0 = *(const float4*)&Xs[jj][ci];
            float4 b1 = *(const float4*)&Xs[jj][ci+4];
            float bv[8] = {b0.x,b0.y,b0.z,b0.w,b1.x,b1.y,b1.z,b1.w};
#pragma unroll
            for (int y = 0; y < 8; y++) {
                acc[0][y] = fmaf(a0, bv[y], acc[0][y]);
                acc[1][y] = fmaf(a1, bv[y], acc[1][y]);
            }
        }
        __syncthreads();
    }
#pragma unroll
    for (int r = 0; r < 2; r++) {
        float* cp = &g_ctx[(b*SS + i0 + ri + r)*128 + ci];
        *(float4*)cp     = make_float4(acc[r][0],acc[r][1],acc[r][2],acc[r][3]);
        *(float4*)(cp+4) = make_float4(acc[r][4],acc[r][5],acc[r][6],acc[r][7]);
    }
}

// ---------------- x = X + context @ W_ctx^T ---------------------------------
__global__ __launch_bounds__(256) void k_ctxproj()
{
    int tt = threadIdx.x >> 7, d = threadIdx.x & 127;
    int tok = blockIdx.x * 2 + tt;
    __shared__ float cs[2][128];
    cs[tt][d] = g_ctx[tok*128 + d];
    __syncthreads();
    float acc = 0.f;
#pragma unroll 8
    for (int e = 0; e < 128; e++) acc = fmaf(cs[tt][e], g_WctxT[e*128 + d], acc);
    g_x[tok*128 + d] = g_X[tok*128 + d] + acc;
}

// ---------------- phasor sums -------------------------------------------------
__global__ __launch_bounds__(256) void k_sincos()
{
    int tt = threadIdx.x >> 7, n = threadIdx.x & 127;
    int tok = blockIdx.x * 2 + tt;
    __shared__ float xs[2][128];
    xs[tt][n] = g_x[tok*128 + n];
    __syncthreads();
    float Ca = 0.f, Sa = 0.f;
#pragma unroll 4
    for (int d = 0; d < 128; d++) {
        float a = fmaf(xs[tt][d], g_rres[d*128 + n], g_bres[d*128 + n]);
        float s, c; __sincosf(a, &s, &c);
        Ca += c; Sa += s;
    }
    int sidx = tok & (SS-1);
    float cT = g_tcos[sidx], sT = g_tsin[sidx];
    g_cs  [tok*128 + n] = cT*Ca - sT*Sa;
    g_ssum[tok*128 + n] = cT*Sa + sT*Ca;
}

// ---------------- silu residual + split-bf16 write ---------------------------
__global__ __launch_bounds__(256) void k_silu()
{
    int tt = threadIdx.x >> 7, d = threadIdx.x & 127;
    int tok = blockIdx.x * 2 + tt;
    __shared__ float cs[2][128];
    __shared__ float ss[2][128];
    cs[tt][d] = g_cs  [tok*128 + d];
    ss[tt][d] = g_ssum[tok*128 + d];
    __syncthreads();
    float acc = 0.f;
#pragma unroll 4
    for (int n = 0; n < 128; n++) {
        acc = fmaf(cs[tt][n], g_WrealT[n*128 + d], acc);
        acc = fmaf(ss[tt][n], g_WimagT[n*128 + d], acc);
    }
    float sv = acc / (1.0f + expf(-acc));
    float xv = g_x[tok*128 + d] + sv;
    __nv_bfloat16 hi = __float2bfloat16(xv);
    __nv_bfloat16 lo = __float2bfloat16(xv - __bfloat162float(hi));
    g_xsplit[tok*GK + d]       = hi;   // chunk0: x_hi * w_hi
    g_xsplit[tok*GK + 128 + d] = hi;   // chunk1: x_hi * w_lo
    g_xsplit[tok*GK + 256 + d] = lo;   // chunk2: x_lo * w_hi
}

// ---------------- split W_out ------------------------------------------------
__global__ void k_split_w(const float* __restrict__ W)
{
    int gid = blockIdx.x * 256 + threadIdx.x;   // < 4,096,000
    int n = gid >> 7, k = gid & 127;
    float w = W[gid];
    __nv_bfloat16 hi = __float2bfloat16(w);
    __nv_bfloat16 lo = __float2bfloat16(w - __bfloat162float(hi));
    g_wsplit[n*GK + k]       = hi;
    g_wsplit[n*GK + 128 + k] = lo;
    g_wsplit[n*GK + 256 + k] = hi;
}

// ---------------- mma.sync GEMM: out[4096,32000] = A'[4096,384] @ B'[32000,384]^T
// block 128M x 128N, 8 warps of 64x32, K chunks of 64 bf16, 2-stage cp.async.
__global__ __launch_bounds__(256, 2) void k_gemm_mma(float* __restrict__ out)
{
    extern __shared__ __align__(16) __nv_bfloat16 smem_g[];
    // sA: [2][128*64], sB: [2][128*64]   (each stage 16 KB, total 64 KB)
    const uint32_t saA = smem_u32(smem_g);
    const uint32_t saB = saA + 32768u;

    const int tid  = threadIdx.x;
    const int wid  = tid >> 5;
    const int lane = tid & 31;
    const int bn = blockIdx.x * 128;
    const int bm = blockIdx.y * 128;
    const int wm = (wid >> 2) * 64;     // 0 / 64
    const int wn = (wid & 3) * 32;      // 0..96

    // cp.async source/dest precompute: idx = it*256+tid ; row = idx>>3 ; c = idx&7
    // smem byte offset = row*128 + ((c ^ (row&7))*16)
    float acc[4][4][4];
#pragma unroll
    for (int i = 0; i < 4; i++)
#pragma unroll
        for (int j = 0; j < 4; j++)
#pragma unroll
            for (int q = 0; q < 4; q++) acc[i][j][q] = 0.f;

    auto load_chunk = [&](int ch, int buf) {
#pragma unroll
        for (int it = 0; it < 4; ++it) {
            int idx = it*256 + tid;
            int row = idx >> 3, c = idx & 7;
            uint32_t soff = (uint32_t)(row*128 + ((c ^ (row & 7))*16));
            const void* gA = (const void*)(g_xsplit + (size_t)(bm+row)*GK + ch*64 + c*8);
            const void* gB = (const void*)(g_wsplit + (size_t)(bn+row)*GK + ch*64 + c*8);
            uint32_t dA = saA + (uint32_t)buf*16384u + soff;
            uint32_t dB = saB + (uint32_t)buf*16384u + soff;
            asm volatile("cp.async.cg.shared.global [%0], [%1], 16;" :: "r"(dA), "l"(gA));
            asm volatile("cp.async.cg.shared.global [%0], [%1], 16;" :: "r"(dB), "l"(gB));
        }
        asm volatile("cp.async.commit_group;");
    };

    load_chunk(0, 0);
    load_chunk(1, 1);

    const int rsel = lane & 15;          // row-within-16 for ldmatrix
    const int csel = lane >> 4;          // 16B half selector
    const int rpar = lane & 7;           // row parity for swizzle

#pragma unroll 1
    for (int ch = 0; ch < 6; ++ch) {
        if (ch == 5) asm volatile("cp.async.wait_group 0;");
        else         asm volatile("cp.async.wait_group 1;");
        __syncthreads();
        const uint32_t bA = saA + (uint32_t)(ch & 1)*16384u;
        const uint32_t bB = saB + (uint32_t)(ch & 1)*16384u;
#pragma unroll
        for (int ks = 0; ks < 4; ++ks) {
            const uint32_t xoff = (uint32_t)(((ks*2 + csel) ^ rpar) * 16);
            uint32_t a[4][4];
#pragma unroll
            for (int mf = 0; mf < 4; ++mf) {
                uint32_t addr = bA + (uint32_t)((wm + mf*16 + rsel)*128) + xoff;
                asm volatile("ldmatrix.sync.aligned.m8n8.x4.shared.b16 {%0,%1,%2,%3}, [%4];"
                             : "=r"(a[mf][0]), "=r"(a[mf][1]), "=r"(a[mf][2]), "=r"(a[mf][3])
                             : "r"(addr));
            }
            uint32_t b[2][4];
#pragma unroll
            for (int p = 0; p < 2; ++p) {
                uint32_t addr = bB + (uint32_t)((wn + p*16 + rsel)*128) + xoff;
                asm volatile("ldmatrix.sync.aligned.m8n8.x4.shared.b16 {%0,%1,%2,%3}, [%4];"
                             : "=r"(b[p][0]), "=r"(b[p][1]), "=r"(b[p][2]), "=r"(b[p][3])
                             : "r"(addr));
            }
#pragma unroll
            for (int mf = 0; mf < 4; ++mf)
#pragma unroll
                for (int nt = 0; nt < 4; ++nt) {
                    uint32_t b0 = b[nt >> 1][(nt & 1)];
                    uint32_t b1 = b[nt >> 1][(nt & 1) + 2];
                    asm volatile(
                        "mma.sync.aligned.m16n8k16.row.col.f32.bf16.bf16.f32 "
                        "{%0,%1,%2,%3}, {%4,%5,%6,%7}, {%8,%9}, {%0,%1,%2,%3};"
                        : "+f"(acc[mf][nt][0]), "+f"(acc[mf][nt][1]),
                          "+f"(acc[mf][nt][2]), "+f"(acc[mf][nt][3])
                        : "r"(a[mf][0]), "r"(a[mf][1]), "r"(a[mf][2]), "r"(a[mf][3]),
                          "r"(b0), "r"(b1));
                }
        }
        __syncthreads();
        if (ch + 2 < 6) load_chunk(ch + 2, ch & 1);
    }

    // epilogue
    const int erow = bm + wm + (lane >> 2);
    const int ecol = bn + wn + (lane & 3)*2;
#pragma unroll
    for (int mf = 0; mf < 4; ++mf) {
#pragma unroll
        for (int nt = 0; nt < 4; ++nt) {
            float* p0 = out + (size_t)(erow + mf*16)     * VV + ecol + nt*8;
            float* p1 = out + (size_t)(erow + mf*16 + 8) * VV + ecol + nt*8;
            *(float2*)p0 = make_float2(acc[mf][nt][0], acc[mf][nt][1]);
            *(float2*)p1 = make_float2(acc[mf][nt][2], acc[mf][nt][3]);
        }
    }
}

// ---------------- launch ------------------------------------------------------
extern "C" void kernel_launch(void* const* d_in, const int* in_sizes, int n_in,
                              void* d_out, int out_size)
{
    const int*   ids   = (const int*)  d_in[0];
    const float* emb   = (const float*)d_in[1];
    const float* wq    = (const float*)d_in[2];
    const float* bq    = (const float*)d_in[3];
    const float* wk    = (const float*)d_in[4];
    const float* bk    = (const float*)d_in[5];
    const float* Wctx  = (const float*)d_in[6];
    const float* Wres  = (const float*)d_in[7];
    const float* Bres  = (const float*)d_in[8];
    const float* Wreal = (const float*)d_in[9];
    const float* Wimag = (const float*)d_in[10];
    const float* Wout  = (const float*)d_in[11];
    float* out = (float*)d_out;

    const int GEMM_SMEM = 65536;   // 2-stage A+B tiles
    cudaFuncSetAttribute(k_gemm_mma, cudaFuncAttributeMaxDynamicSharedMemorySize, GEMM_SMEM);

    k_prep    <<<64,   256>>>(Wctx, Wres, Bres, Wreal, Wimag);
    k_split_w <<<16000,256>>>(Wout);
    k_gather  <<<2048, 256>>>(ids, emb);
    k_scan    <<<4,    128>>>();
    k_qk      <<<2048, 256>>>(wq, bq, wk, bk);
    k_scores  <<<dim3(16, 16, 32), 256>>>();
    k_softmax <<<dim3(1024, 4),    256>>>();
    k_ctxgemm <<<dim3(32, 4),      256>>>();
    k_ctxproj <<<2048, 256>>>();
    k_sincos  <<<2048, 256>>>();
    k_silu    <<<2048, 256>>>();
    k_gemm_mma<<<dim3(VV/128, TOK/128), 256, GEMM_SMEM>>>(out);
    (void)in_sizes; (void)n_in; (void)out_size;
}